// round 3
// baseline (speedup 1.0000x reference)
#include <cuda_runtime.h>
#include <math.h>
#include <stdint.h>

#define BSZ   1024
#define NP    256
#define DIM   128
#define TB    51200      // triplets per batch segment (T1 == T3)
#define TL    12800      // triplets per lca segment   (T2 == T4)
#define TTOT  (2*TB + 2*TL)
#define NGBLK (TTOT / 8)

// ---------------- scratch (static device globals; no allocation) ------------
__device__ float  g_lh[NP * DIM];    // poincare-mapped lcas, row-major
__device__ float  g_lhT[DIM * NP];   // transposed for coalesced dist loads
__device__ float  g_y2[NP];          // ||lh||^2 per proxy
__device__ float  g_Dz[BSZ * NP];    // dist(z_s, lh)
__device__ float  g_Dt[BSZ * NP];    // dist(t_s, lh)
__device__ float  g_Dll[NP * NP];    // dist(lh, lh)
__device__ double g_accum;           // loss accumulator (fp64)
__device__ unsigned int g_ticket;    // last-block-done counter

// ---------------- to_poincare (also resets accum + ticket) ------------------
__global__ void k_poincare(const float* __restrict__ lcas) {
    const int r = blockIdx.x;
    const int d = threadIdx.x;
    if (r == 0 && d == 0) { g_accum = 0.0; g_ticket = 0u; }
    __shared__ float red[DIM];

    float x = lcas[r * DIM + d];

    red[d] = x * x; __syncthreads();
    #pragma unroll
    for (int s = 64; s > 0; s >>= 1) { if (d < s) red[d] += red[d + s]; __syncthreads(); }
    float xn = sqrtf(red[0]) + 1e-5f;
    __syncthreads();

    x *= fminf(1.0f, 2.3f / xn);

    red[d] = x * x; __syncthreads();
    #pragma unroll
    for (int s = 64; s > 0; s >>= 1) { if (d < s) red[d] += red[d + s]; __syncthreads(); }
    float xn2 = fmaxf(sqrtf(red[0]), 1e-5f);
    __syncthreads();

    const float sqrt_c = 0.31622776601683794f;   // sqrt(0.1)
    float arg = sqrt_c * xn2;
    x = tanhf(arg) * x / arg;                    // expmap0

    red[d] = x * x; __syncthreads();
    #pragma unroll
    for (int s = 64; s > 0; s >>= 1) { if (d < s) red[d] += red[d + s]; __syncthreads(); }
    float n3 = fmaxf(sqrtf(red[0]), 1e-5f);
    __syncthreads();
    const float maxn = (1.0f - 1e-3f) / 0.31622776601683794f;
    if (n3 > maxn) x = x / n3 * maxn;

    red[d] = x * x; __syncthreads();
    #pragma unroll
    for (int s = 64; s > 0; s >>= 1) { if (d < s) red[d] += red[d + s]; __syncthreads(); }

    g_lh[r * DIM + d]  = x;
    g_lhT[d * NP + r]  = x;
    if (d == 0) g_y2[r] = red[0];
}

// ---------------- fused distance matrices -----------------------------------
// 8 source rows per block, 256 threads (one per proxy column).
// blocks: [0,128) -> z rows, [128,256) -> t rows, [256,288) -> lh rows.
__global__ __launch_bounds__(256) void k_dist_all(const float* __restrict__ z,
                                                  const float* __restrict__ t) {
    __shared__ float xs[8 * DIM];
    __shared__ float sx2[8];
    const int b   = blockIdx.x;
    const int tid = threadIdx.x;

    const float* __restrict__ X;
    float* __restrict__ out;
    int r0;
    if (b < 128)      { X = z;    out = g_Dz;  r0 = b * 8; }
    else if (b < 256) { X = t;    out = g_Dt;  r0 = (b - 128) * 8; }
    else              { X = g_lh; out = g_Dll; r0 = (b - 256) * 8; }

    #pragma unroll
    for (int idx = tid; idx < 8 * DIM; idx += 256)
        xs[idx] = X[r0 * DIM + idx];
    __syncthreads();

    const int warp = tid >> 5, lane = tid & 31;
    {
        float s = 0.0f;
        #pragma unroll
        for (int q = 0; q < 4; ++q) {
            float e = xs[warp * DIM + lane + 32 * q];
            s = fmaf(e, e, s);
        }
        #pragma unroll
        for (int off = 16; off > 0; off >>= 1)
            s += __shfl_down_sync(0xffffffffu, s, off);
        if (lane == 0) sx2[warp] = s;
    }
    __syncthreads();

    const int col = tid;
    float acc[8] = {0,0,0,0,0,0,0,0};
    #pragma unroll 4
    for (int d = 0; d < DIM; ++d) {
        float yv = g_lhT[d * NP + col];
        #pragma unroll
        for (int r = 0; r < 8; ++r)
            acc[r] = fmaf(xs[r * DIM + d], yv, acc[r]);
    }

    const float y2 = g_y2[col];
    const float c  = 0.1f;
    #pragma unroll
    for (int r = 0; r < 8; ++r) {
        float x2    = sx2[r];
        float xy    = -acc[r];                               // (-x).y
        float a     = 1.0f + 2.0f * c * xy + c * y2;
        float bb    = 1.0f - c * x2;
        float denom = 1.0f + 2.0f * c * xy + (c * c) * x2 * y2;
        float numsq = a * a * x2 + 2.0f * a * bb * xy + bb * bb * y2;
        float nrm   = sqrtf(fmaxf(numsq, 1e-12f)) / fabsf(denom + 1e-5f);
        float v = 0.31622776601683794f * nrm;
        v = fminf(fmaxf(v, -0.99999f), 0.99999f);
        float art = 0.5f * (log1pf(v) - log1pf(-v));
        out[(r0 + r) * NP + col] = 6.324555320336759f * art;
    }
}

// ---------------- fused ghhc over all 4 triplet sets -------------------------
// One warp per triplet; lane owns 8 contiguous proxies. All 10 float4 loads
// are issued up front (MLP=10), then consumed. Last block writes the result.
__global__ __launch_bounds__(256, 4) void k_ghhc_all(
    const int*  __restrict__ t1, const int*  __restrict__ t2,
    const int*  __restrict__ t3, const int*  __restrict__ t4,
    const float* __restrict__ G1, const float* __restrict__ G2,
    const float* __restrict__ G3, const float* __restrict__ G4,
    float* __restrict__ outp) {
    __shared__ double wsum[8];
    const int warp = threadIdx.x >> 5;
    const int lane = threadIdx.x & 31;
    const int w    = blockIdx.x * 8 + warp;

    const int* trip; const float* g; const float* D; int T, t; double invT;
    if (w < TB)                { trip = t1; g = G1; D = g_Dz;  T = TB; t = w;                 invT = 1.0 / TB; }
    else if (w < TB + TL)      { trip = t2; g = G2; D = g_Dll; T = TL; t = w - TB;            invT = 1.0 / TL; }
    else if (w < 2*TB + TL)    { trip = t3; g = G3; D = g_Dt;  T = TB; t = w - (TB + TL);     invT = 1.0 / TB; }
    else                       { trip = t4; g = G4; D = g_Dll; T = TL; t = w - (2*TB + TL);   invT = 1.0 / TL; }

    const int i = trip[t];
    const int j = trip[T + t];
    const int k = trip[2 * T + t];
    const float* __restrict__ di = D + (size_t)i * NP;
    const float* __restrict__ dj = D + (size_t)j * NP;
    const float* __restrict__ dk = D + (size_t)k * NP;
    const float* __restrict__ g0 = g + (size_t)t * NP;
    const float* __restrict__ g1 = g + ((size_t)T + t) * NP;
    const int base = lane * 8;

    // ---- all loads up front: 10 independent float4s in flight ----
    float4 a0 = *(const float4*)(di + base), a1 = *(const float4*)(di + base + 4);
    float4 b0 = *(const float4*)(dj + base), b1 = *(const float4*)(dj + base + 4);
    float4 c0 = *(const float4*)(dk + base), c1 = *(const float4*)(dk + base + 4);
    float4 e0 = *(const float4*)(g0 + base), e1 = *(const float4*)(g0 + base + 4);
    float4 f0 = *(const float4*)(g1 + base), f1 = *(const float4*)(g1 + base + 4);

    float av[8] = {a0.x, a0.y, a0.z, a0.w, a1.x, a1.y, a1.z, a1.w};
    float bv[8] = {b0.x, b0.y, b0.z, b0.w, b1.x, b1.y, b1.z, b1.w};
    float cv[8] = {c0.x, c0.y, c0.z, c0.w, c1.x, c1.y, c1.z, c1.w};
    float ev[8] = {e0.x, e0.y, e0.z, e0.w, e1.x, e1.y, e1.z, e1.w};
    float fv[8] = {f0.x, f0.y, f0.z, f0.w, f1.x, f1.y, f1.z, f1.w};

    float best0 = -INFINITY, best1 = -INFINITY;
    int   idx0 = 0, idx1 = 0;
    #pragma unroll
    for (int u = 0; u < 8; ++u) {
        float m  = fmaxf(av[u], bv[u]);               // max(di, dj)
        float s0 = fmaf(m, -10.0f, ev[u]);            // g - max/tau
        if (s0 > best0) { best0 = s0; idx0 = base + u; }
        float m2 = fmaxf(cv[u], m);                   // max(dk, max_ij)
        float s1 = fmaf(m2, -10.0f, fv[u]);
        if (s1 > best1) { best1 = s1; idx1 = base + u; }
    }

    // warp argmax reduce, first-occurrence (lowest index) wins ties
    #pragma unroll
    for (int off = 16; off > 0; off >>= 1) {
        float ov = __shfl_down_sync(0xffffffffu, best0, off);
        int   oi = __shfl_down_sync(0xffffffffu, idx0,  off);
        if (ov > best0 || (ov == best0 && oi < idx0)) { best0 = ov; idx0 = oi; }
        float ow = __shfl_down_sync(0xffffffffu, best1, off);
        int   oj = __shfl_down_sync(0xffffffffu, idx1,  off);
        if (ow > best1 || (ow == best1 && oj < idx1)) { best1 = ow; idx1 = oj; }
    }

    double hc = 0.0;
    if (lane == 0 && idx0 != idx1) {                  // diff_lca gate
        float dia = di[idx0], dib = di[idx1];
        float dja = dj[idx0], djb = dj[idx1];
        float dka = dk[idx0], dkb = dk[idx1];
        float h = fmaxf(dia - dib + 0.1f, 0.0f)
                + fmaxf(dja - djb + 0.1f, 0.0f)
                + fmaxf(dkb - dka + 0.1f, 0.0f);
        hc = (double)h * invT;
    }
    if (lane == 0) wsum[warp] = hc;
    __syncthreads();

    if (threadIdx.x == 0) {
        double s = 0.0;
        #pragma unroll
        for (int q = 0; q < 8; ++q) s += wsum[q];
        atomicAdd(&g_accum, s);
        __threadfence();
        unsigned int rank = atomicInc(&g_ticket, 0xffffffffu);
        if (rank == NGBLK - 1) {                      // last block done
            __threadfence();
            outp[0] = (float)g_accum;
        }
    }
}

// ---------------- launch -----------------------------------------------------
extern "C" void kernel_launch(void* const* d_in, const int* in_sizes, int n_in,
                              void* d_out, int out_size) {
    const float* z_s   = (const float*)d_in[0];
    const float* t_s   = (const float*)d_in[1];
    /* d_in[2] = y, unused */
    const float* lcas  = (const float*)d_in[3];
    const int*   trip1 = (const int*)d_in[4];
    const int*   trip2 = (const int*)d_in[5];
    const int*   trip3 = (const int*)d_in[6];
    const int*   trip4 = (const int*)d_in[7];
    const float* g1    = (const float*)d_in[8];
    const float* g2    = (const float*)d_in[9];
    const float* g3    = (const float*)d_in[10];
    const float* g4    = (const float*)d_in[11];

    k_poincare<<<NP, DIM>>>(lcas);
    k_dist_all<<<288, 256>>>(z_s, t_s);
    k_ghhc_all<<<NGBLK, 256>>>(trip1, trip2, trip3, trip4,
                               g1, g2, g3, g4, (float*)d_out);
}

// round 4
// speedup vs baseline: 1.0003x; 1.0003x over previous
#include <cuda_runtime.h>
#include <math.h>
#include <stdint.h>

#define BSZ   1024
#define NP    256
#define DIM   128
#define TB    51200      // triplets per batch segment (T1 == T3)
#define TL    12800      // triplets per lca segment   (T2 == T4)
#define TTOT  (2*TB + 2*TL)
#define NGBLK (TTOT / 8)

// ---------------- scratch (static device globals; no allocation) ------------
__device__ float  g_lh[NP * DIM];    // poincare-mapped lcas, row-major
__device__ float  g_lhT[DIM * NP];   // transposed for coalesced dist loads
__device__ float  g_y2[NP];          // ||lh||^2 per proxy
__device__ float  g_Dz[BSZ * NP];    // dist(z_s, lh)
__device__ float  g_Dt[BSZ * NP];    // dist(t_s, lh)
__device__ float  g_Dll[NP * NP];    // dist(lh, lh)
__device__ double g_accum;           // loss accumulator (fp64)
__device__ unsigned int g_ticket;    // last-block-done counter

// ---------------- to_poincare: warp per row, shuffle reductions --------------
// 8 warps/block, 32 blocks. Lane l owns elems l, l+32, l+64, l+96.
__global__ __launch_bounds__(256) void k_poincare(const float* __restrict__ lcas) {
    const int warp = threadIdx.x >> 5;
    const int lane = threadIdx.x & 31;
    const int r    = blockIdx.x * 8 + warp;
    if (blockIdx.x == 0 && threadIdx.x == 0) { g_accum = 0.0; g_ticket = 0u; }

    float x[4];
    #pragma unroll
    for (int q = 0; q < 4; ++q) x[q] = lcas[r * DIM + lane + 32 * q];

    // ||x||
    float s = 0.0f;
    #pragma unroll
    for (int q = 0; q < 4; ++q) s = fmaf(x[q], x[q], s);
    #pragma unroll
    for (int off = 16; off > 0; off >>= 1) s += __shfl_xor_sync(0xffffffffu, s, off);
    float xn = sqrtf(s) + 1e-5f;

    float scale = fminf(1.0f, 2.3f / xn);
    #pragma unroll
    for (int q = 0; q < 4; ++q) x[q] *= scale;

    // ||clipped x||
    s = 0.0f;
    #pragma unroll
    for (int q = 0; q < 4; ++q) s = fmaf(x[q], x[q], s);
    #pragma unroll
    for (int off = 16; off > 0; off >>= 1) s += __shfl_xor_sync(0xffffffffu, s, off);
    float xn2 = fmaxf(sqrtf(s), 1e-5f);

    const float sqrt_c = 0.31622776601683794f;   // sqrt(0.1)
    float arg = sqrt_c * xn2;
    float es  = tanhf(arg) / arg;                // expmap0 scale
    #pragma unroll
    for (int q = 0; q < 4; ++q) x[q] *= es;

    // project
    s = 0.0f;
    #pragma unroll
    for (int q = 0; q < 4; ++q) s = fmaf(x[q], x[q], s);
    #pragma unroll
    for (int off = 16; off > 0; off >>= 1) s += __shfl_xor_sync(0xffffffffu, s, off);
    float n3 = fmaxf(sqrtf(s), 1e-5f);
    const float maxn = (1.0f - 1e-3f) / 0.31622776601683794f;
    if (n3 > maxn) {
        float ps = maxn / n3;
        #pragma unroll
        for (int q = 0; q < 4; ++q) x[q] *= ps;
        s *= ps * ps;
    }

    #pragma unroll
    for (int q = 0; q < 4; ++q) {
        g_lh[r * DIM + lane + 32 * q]   = x[q];
        g_lhT[(lane + 32 * q) * NP + r] = x[q];
    }
    if (lane == 0) g_y2[r] = s;
}

// ---------------- fused distance matrices -----------------------------------
// 8 source rows per block, 256 threads (one per proxy column).
// blocks: [0,128) -> z rows, [128,256) -> t rows, [256,288) -> lh rows.
__global__ __launch_bounds__(256) void k_dist_all(const float* __restrict__ z,
                                                  const float* __restrict__ t) {
    __shared__ float xs[8 * DIM];
    __shared__ float sx2[8];
    const int b   = blockIdx.x;
    const int tid = threadIdx.x;

    const float* __restrict__ X;
    float* __restrict__ out;
    int r0;
    if (b < 128)      { X = z;    out = g_Dz;  r0 = b * 8; }
    else if (b < 256) { X = t;    out = g_Dt;  r0 = (b - 128) * 8; }
    else              { X = g_lh; out = g_Dll; r0 = (b - 256) * 8; }

    #pragma unroll
    for (int idx = tid; idx < 8 * DIM; idx += 256)
        xs[idx] = X[r0 * DIM + idx];
    __syncthreads();

    const int warp = tid >> 5, lane = tid & 31;
    {
        float s = 0.0f;
        #pragma unroll
        for (int q = 0; q < 4; ++q) {
            float e = xs[warp * DIM + lane + 32 * q];
            s = fmaf(e, e, s);
        }
        #pragma unroll
        for (int off = 16; off > 0; off >>= 1)
            s += __shfl_down_sync(0xffffffffu, s, off);
        if (lane == 0) sx2[warp] = s;
    }
    __syncthreads();

    const int col = tid;
    float acc[8] = {0,0,0,0,0,0,0,0};
    #pragma unroll 4
    for (int d = 0; d < DIM; ++d) {
        float yv = g_lhT[d * NP + col];
        #pragma unroll
        for (int r = 0; r < 8; ++r)
            acc[r] = fmaf(xs[r * DIM + d], yv, acc[r]);
    }

    const float y2 = g_y2[col];
    const float c  = 0.1f;
    #pragma unroll
    for (int r = 0; r < 8; ++r) {
        float x2    = sx2[r];
        float xy    = -acc[r];                               // (-x).y
        float a     = 1.0f + 2.0f * c * xy + c * y2;
        float bb    = 1.0f - c * x2;
        float denom = 1.0f + 2.0f * c * xy + (c * c) * x2 * y2;
        float numsq = a * a * x2 + 2.0f * a * bb * xy + bb * bb * y2;
        float nrm   = sqrtf(fmaxf(numsq, 1e-12f)) / fabsf(denom + 1e-5f);
        float v = 0.31622776601683794f * nrm;
        v = fminf(fmaxf(v, -0.99999f), 0.99999f);
        float art = 0.5f * (log1pf(v) - log1pf(-v));
        out[(r0 + r) * NP + col] = 6.324555320336759f * art;
    }
}

// ---------------- fused ghhc over all 4 triplet sets -------------------------
// One warp per triplet; lane owns 8 contiguous proxies. Phase-split to keep
// register liveness under the 64-reg / 4-block budget (NO spills).
__global__ __launch_bounds__(256, 4) void k_ghhc_all(
    const int*  __restrict__ t1, const int*  __restrict__ t2,
    const int*  __restrict__ t3, const int*  __restrict__ t4,
    const float* __restrict__ G1, const float* __restrict__ G2,
    const float* __restrict__ G3, const float* __restrict__ G4,
    float* __restrict__ outp) {
    __shared__ double wsum[8];
    const int warp = threadIdx.x >> 5;
    const int lane = threadIdx.x & 31;
    const int w    = blockIdx.x * 8 + warp;

    const int* trip; const float* g; const float* D; int T, t; double invT;
    if (w < TB)                { trip = t1; g = G1; D = g_Dz;  T = TB; t = w;                 invT = 1.0 / TB; }
    else if (w < TB + TL)      { trip = t2; g = G2; D = g_Dll; T = TL; t = w - TB;            invT = 1.0 / TL; }
    else if (w < 2*TB + TL)    { trip = t3; g = G3; D = g_Dt;  T = TB; t = w - (TB + TL);     invT = 1.0 / TB; }
    else                       { trip = t4; g = G4; D = g_Dll; T = TL; t = w - (2*TB + TL);   invT = 1.0 / TL; }

    const int i = trip[t];
    const int j = trip[T + t];
    const int k = trip[2 * T + t];
    const float* __restrict__ di = D + (size_t)i * NP;
    const float* __restrict__ dj = D + (size_t)j * NP;
    const float* __restrict__ dk = D + (size_t)k * NP;
    const float* __restrict__ g0 = g + (size_t)t * NP;
    const float* __restrict__ g1 = g + ((size_t)T + t) * NP;
    const int base = lane * 8;

    float m[8];
    float best0 = -INFINITY, best1 = -INFINITY;
    int   idx0 = 0, idx1 = 0;

    // ---- phase A: di, dj, g0 -> max_ij, score0 ----
    {
        float4 a0 = *(const float4*)(di + base), a1 = *(const float4*)(di + base + 4);
        float4 b0 = *(const float4*)(dj + base), b1 = *(const float4*)(dj + base + 4);
        float4 e0 = *(const float4*)(g0 + base), e1 = *(const float4*)(g0 + base + 4);
        float av[8] = {a0.x, a0.y, a0.z, a0.w, a1.x, a1.y, a1.z, a1.w};
        float bv[8] = {b0.x, b0.y, b0.z, b0.w, b1.x, b1.y, b1.z, b1.w};
        float ev[8] = {e0.x, e0.y, e0.z, e0.w, e1.x, e1.y, e1.z, e1.w};
        #pragma unroll
        for (int u = 0; u < 8; ++u) {
            m[u] = fmaxf(av[u], bv[u]);
            float s0 = fmaf(m[u], -10.0f, ev[u]);     // g - max/tau
            if (s0 > best0) { best0 = s0; idx0 = base + u; }
        }
    }
    // ---- phase B: dk, g1 -> max_ijk, score1 ----
    {
        float4 c0 = *(const float4*)(dk + base), c1 = *(const float4*)(dk + base + 4);
        float4 f0 = *(const float4*)(g1 + base), f1 = *(const float4*)(g1 + base + 4);
        float cv[8] = {c0.x, c0.y, c0.z, c0.w, c1.x, c1.y, c1.z, c1.w};
        float fv[8] = {f0.x, f0.y, f0.z, f0.w, f1.x, f1.y, f1.z, f1.w};
        #pragma unroll
        for (int u = 0; u < 8; ++u) {
            float m2 = fmaxf(cv[u], m[u]);
            float s1 = fmaf(m2, -10.0f, fv[u]);
            if (s1 > best1) { best1 = s1; idx1 = base + u; }
        }
    }

    // warp argmax reduce, first-occurrence (lowest index) wins ties
    #pragma unroll
    for (int off = 16; off > 0; off >>= 1) {
        float ov = __shfl_down_sync(0xffffffffu, best0, off);
        int   oi = __shfl_down_sync(0xffffffffu, idx0,  off);
        if (ov > best0 || (ov == best0 && oi < idx0)) { best0 = ov; idx0 = oi; }
        float ow = __shfl_down_sync(0xffffffffu, best1, off);
        int   oj = __shfl_down_sync(0xffffffffu, idx1,  off);
        if (ow > best1 || (ow == best1 && oj < idx1)) { best1 = ow; idx1 = oj; }
    }

    double hc = 0.0;
    if (lane == 0 && idx0 != idx1) {                  // diff_lca gate
        float dia = di[idx0], dib = di[idx1];
        float dja = dj[idx0], djb = dj[idx1];
        float dka = dk[idx0], dkb = dk[idx1];
        float h = fmaxf(dia - dib + 0.1f, 0.0f)
                + fmaxf(dja - djb + 0.1f, 0.0f)
                + fmaxf(dkb - dka + 0.1f, 0.0f);
        hc = (double)h * invT;
    }
    if (lane == 0) wsum[warp] = hc;
    __syncthreads();

    if (threadIdx.x == 0) {
        double s = 0.0;
        #pragma unroll
        for (int q = 0; q < 8; ++q) s += wsum[q];
        atomicAdd(&g_accum, s);
        __threadfence();
        unsigned int rank = atomicInc(&g_ticket, 0xffffffffu);
        if (rank == NGBLK - 1) {                      // last block done
            __threadfence();
            outp[0] = (float)g_accum;
        }
    }
}

// ---------------- launch -----------------------------------------------------
extern "C" void kernel_launch(void* const* d_in, const int* in_sizes, int n_in,
                              void* d_out, int out_size) {
    const float* z_s   = (const float*)d_in[0];
    const float* t_s   = (const float*)d_in[1];
    /* d_in[2] = y, unused */
    const float* lcas  = (const float*)d_in[3];
    const int*   trip1 = (const int*)d_in[4];
    const int*   trip2 = (const int*)d_in[5];
    const int*   trip3 = (const int*)d_in[6];
    const int*   trip4 = (const int*)d_in[7];
    const float* g1    = (const float*)d_in[8];
    const float* g2    = (const float*)d_in[9];
    const float* g3    = (const float*)d_in[10];
    const float* g4    = (const float*)d_in[11];

    k_poincare<<<32, 256>>>(lcas);
    k_dist_all<<<288, 256>>>(z_s, t_s);
    k_ghhc_all<<<NGBLK, 256>>>(trip1, trip2, trip3, trip4,
                               g1, g2, g3, g4, (float*)d_out);
}

// round 5
// speedup vs baseline: 1.4248x; 1.4244x over previous
#include <cuda_runtime.h>
#include <math.h>
#include <stdint.h>

#define BSZ   1024
#define NP    256
#define DIM   128
#define TB    51200      // triplets per batch segment (T1 == T3)
#define TL    12800      // triplets per lca segment   (T2 == T4)
#define TTOT  (2*TB + 2*TL)
#define NGBLK (TTOT / 8)

// ---------------- scratch (static device globals; no allocation) ------------
__device__ float  g_lh[NP * DIM];    // poincare-mapped lcas, row-major
__device__ float  g_lhT[DIM * NP];   // transposed for coalesced dist loads
__device__ float  g_y2[NP];          // ||lh||^2 per proxy
__device__ float  g_Dz[BSZ * NP];    // dist(z_s, lh)
__device__ float  g_Dt[BSZ * NP];    // dist(t_s, lh)
__device__ float  g_Dll[NP * NP];    // dist(lh, lh)
__device__ double g_accum;           // loss accumulator (fp64)

// ---------------- to_poincare: warp per row, shuffle reductions --------------
__global__ __launch_bounds__(256) void k_poincare(const float* __restrict__ lcas) {
    const int warp = threadIdx.x >> 5;
    const int lane = threadIdx.x & 31;
    const int r    = blockIdx.x * 8 + warp;
    if (blockIdx.x == 0 && threadIdx.x == 0) g_accum = 0.0;

    float x[4];
    #pragma unroll
    for (int q = 0; q < 4; ++q) x[q] = lcas[r * DIM + lane + 32 * q];

    float s = 0.0f;
    #pragma unroll
    for (int q = 0; q < 4; ++q) s = fmaf(x[q], x[q], s);
    #pragma unroll
    for (int off = 16; off > 0; off >>= 1) s += __shfl_xor_sync(0xffffffffu, s, off);
    float xn = sqrtf(s) + 1e-5f;

    float scale = fminf(1.0f, 2.3f / xn);
    #pragma unroll
    for (int q = 0; q < 4; ++q) x[q] *= scale;

    s = 0.0f;
    #pragma unroll
    for (int q = 0; q < 4; ++q) s = fmaf(x[q], x[q], s);
    #pragma unroll
    for (int off = 16; off > 0; off >>= 1) s += __shfl_xor_sync(0xffffffffu, s, off);
    float xn2 = fmaxf(sqrtf(s), 1e-5f);

    const float sqrt_c = 0.31622776601683794f;   // sqrt(0.1)
    float arg = sqrt_c * xn2;
    float es  = tanhf(arg) / arg;                // expmap0 scale
    #pragma unroll
    for (int q = 0; q < 4; ++q) x[q] *= es;

    s = 0.0f;
    #pragma unroll
    for (int q = 0; q < 4; ++q) s = fmaf(x[q], x[q], s);
    #pragma unroll
    for (int off = 16; off > 0; off >>= 1) s += __shfl_xor_sync(0xffffffffu, s, off);
    float n3 = fmaxf(sqrtf(s), 1e-5f);
    const float maxn = (1.0f - 1e-3f) / 0.31622776601683794f;
    if (n3 > maxn) {
        float ps = maxn / n3;
        #pragma unroll
        for (int q = 0; q < 4; ++q) x[q] *= ps;
        s *= ps * ps;
    }

    #pragma unroll
    for (int q = 0; q < 4; ++q) {
        g_lh[r * DIM + lane + 32 * q]   = x[q];
        g_lhT[(lane + 32 * q) * NP + r] = x[q];
    }
    if (lane == 0) g_y2[r] = s;
}

// ---------------- fused distance matrices -----------------------------------
__global__ __launch_bounds__(256) void k_dist_all(const float* __restrict__ z,
                                                  const float* __restrict__ t) {
    __shared__ float xs[8 * DIM];
    __shared__ float sx2[8];
    const int b   = blockIdx.x;
    const int tid = threadIdx.x;

    const float* __restrict__ X;
    float* __restrict__ out;
    int r0;
    if (b < 128)      { X = z;    out = g_Dz;  r0 = b * 8; }
    else if (b < 256) { X = t;    out = g_Dt;  r0 = (b - 128) * 8; }
    else              { X = g_lh; out = g_Dll; r0 = (b - 256) * 8; }

    #pragma unroll
    for (int idx = tid; idx < 8 * DIM; idx += 256)
        xs[idx] = X[r0 * DIM + idx];
    __syncthreads();

    const int warp = tid >> 5, lane = tid & 31;
    {
        float s = 0.0f;
        #pragma unroll
        for (int q = 0; q < 4; ++q) {
            float e = xs[warp * DIM + lane + 32 * q];
            s = fmaf(e, e, s);
        }
        #pragma unroll
        for (int off = 16; off > 0; off >>= 1)
            s += __shfl_down_sync(0xffffffffu, s, off);
        if (lane == 0) sx2[warp] = s;
    }
    __syncthreads();

    const int col = tid;
    float acc[8] = {0,0,0,0,0,0,0,0};
    #pragma unroll 4
    for (int d = 0; d < DIM; ++d) {
        float yv = g_lhT[d * NP + col];
        #pragma unroll
        for (int r = 0; r < 8; ++r)
            acc[r] = fmaf(xs[r * DIM + d], yv, acc[r]);
    }

    const float y2 = g_y2[col];
    const float c  = 0.1f;
    #pragma unroll
    for (int r = 0; r < 8; ++r) {
        float x2    = sx2[r];
        float xy    = -acc[r];                               // (-x).y
        float a     = 1.0f + 2.0f * c * xy + c * y2;
        float bb    = 1.0f - c * x2;
        float denom = 1.0f + 2.0f * c * xy + (c * c) * x2 * y2;
        float numsq = a * a * x2 + 2.0f * a * bb * xy + bb * bb * y2;
        float nrm   = sqrtf(fmaxf(numsq, 1e-12f)) / fabsf(denom + 1e-5f);
        float v = 0.31622776601683794f * nrm;
        v = fminf(fmaxf(v, -0.99999f), 0.99999f);
        float art = 0.5f * (log1pf(v) - log1pf(-v));
        out[(r0 + r) * NP + col] = 6.324555320336759f * art;
    }
}

// ---------------- fused ghhc over all 4 triplet sets -------------------------
// One warp per triplet; lane owns 8 contiguous proxies. Phase-split (no spill).
// Gumbel loads use __ldcs (evict-first): zero-reuse 256MB stream must not
// evict the hot 2.3MB of D matrices from L1/L2.
__global__ __launch_bounds__(256, 4) void k_ghhc_all(
    const int*  __restrict__ t1, const int*  __restrict__ t2,
    const int*  __restrict__ t3, const int*  __restrict__ t4,
    const float* __restrict__ G1, const float* __restrict__ G2,
    const float* __restrict__ G3, const float* __restrict__ G4) {
    __shared__ double wsum[8];
    const int warp = threadIdx.x >> 5;
    const int lane = threadIdx.x & 31;
    const int w    = blockIdx.x * 8 + warp;

    const int* trip; const float* g; const float* D; int T, t; double invT;
    if (w < TB)                { trip = t1; g = G1; D = g_Dz;  T = TB; t = w;                 invT = 1.0 / TB; }
    else if (w < TB + TL)      { trip = t2; g = G2; D = g_Dll; T = TL; t = w - TB;            invT = 1.0 / TL; }
    else if (w < 2*TB + TL)    { trip = t3; g = G3; D = g_Dt;  T = TB; t = w - (TB + TL);     invT = 1.0 / TB; }
    else                       { trip = t4; g = G4; D = g_Dll; T = TL; t = w - (2*TB + TL);   invT = 1.0 / TL; }

    const int i = trip[t];
    const int j = trip[T + t];
    const int k = trip[2 * T + t];
    const float* __restrict__ di = D + (size_t)i * NP;
    const float* __restrict__ dj = D + (size_t)j * NP;
    const float* __restrict__ dk = D + (size_t)k * NP;
    const float* __restrict__ g0 = g + (size_t)t * NP;
    const float* __restrict__ g1 = g + ((size_t)T + t) * NP;
    const int base = lane * 8;

    float m[8];
    float best0 = -INFINITY, best1 = -INFINITY;
    int   idx0 = 0, idx1 = 0;

    // ---- phase A: di, dj, g0 -> max_ij, score0 ----
    {
        float4 a0 = *(const float4*)(di + base), a1 = *(const float4*)(di + base + 4);
        float4 b0 = *(const float4*)(dj + base), b1 = *(const float4*)(dj + base + 4);
        float4 e0 = __ldcs((const float4*)(g0 + base));
        float4 e1 = __ldcs((const float4*)(g0 + base + 4));
        float av[8] = {a0.x, a0.y, a0.z, a0.w, a1.x, a1.y, a1.z, a1.w};
        float bv[8] = {b0.x, b0.y, b0.z, b0.w, b1.x, b1.y, b1.z, b1.w};
        float ev[8] = {e0.x, e0.y, e0.z, e0.w, e1.x, e1.y, e1.z, e1.w};
        #pragma unroll
        for (int u = 0; u < 8; ++u) {
            m[u] = fmaxf(av[u], bv[u]);
            float s0 = fmaf(m[u], -10.0f, ev[u]);     // g - max/tau
            if (s0 > best0) { best0 = s0; idx0 = base + u; }
        }
    }
    // ---- phase B: dk, g1 -> max_ijk, score1 ----
    {
        float4 c0 = *(const float4*)(dk + base), c1 = *(const float4*)(dk + base + 4);
        float4 f0 = __ldcs((const float4*)(g1 + base));
        float4 f1 = __ldcs((const float4*)(g1 + base + 4));
        float cv[8] = {c0.x, c0.y, c0.z, c0.w, c1.x, c1.y, c1.z, c1.w};
        float fv[8] = {f0.x, f0.y, f0.z, f0.w, f1.x, f1.y, f1.z, f1.w};
        #pragma unroll
        for (int u = 0; u < 8; ++u) {
            float m2 = fmaxf(cv[u], m[u]);
            float s1 = fmaf(m2, -10.0f, fv[u]);
            if (s1 > best1) { best1 = s1; idx1 = base + u; }
        }
    }

    // warp argmax reduce, first-occurrence (lowest index) wins ties
    #pragma unroll
    for (int off = 16; off > 0; off >>= 1) {
        float ov = __shfl_down_sync(0xffffffffu, best0, off);
        int   oi = __shfl_down_sync(0xffffffffu, idx0,  off);
        if (ov > best0 || (ov == best0 && oi < idx0)) { best0 = ov; idx0 = oi; }
        float ow = __shfl_down_sync(0xffffffffu, best1, off);
        int   oj = __shfl_down_sync(0xffffffffu, idx1,  off);
        if (ow > best1 || (ow == best1 && oj < idx1)) { best1 = ow; idx1 = oj; }
    }

    double hc = 0.0;
    if (lane == 0 && idx0 != idx1) {                  // diff_lca gate
        float dia = di[idx0], dib = di[idx1];
        float dja = dj[idx0], djb = dj[idx1];
        float dka = dk[idx0], dkb = dk[idx1];
        float h = fmaxf(dia - dib + 0.1f, 0.0f)
                + fmaxf(dja - djb + 0.1f, 0.0f)
                + fmaxf(dkb - dka + 0.1f, 0.0f);
        hc = (double)h * invT;
    }
    if (lane == 0) wsum[warp] = hc;
    __syncthreads();

    if (threadIdx.x == 0) {
        double s = 0.0;
        #pragma unroll
        for (int q = 0; q < 8; ++q) s += wsum[q];
        atomicAdd(&g_accum, s);                       // fire-and-forget
    }
}

__global__ void k_final(float* __restrict__ out) { out[0] = (float)g_accum; }

// ---------------- launch -----------------------------------------------------
extern "C" void kernel_launch(void* const* d_in, const int* in_sizes, int n_in,
                              void* d_out, int out_size) {
    const float* z_s   = (const float*)d_in[0];
    const float* t_s   = (const float*)d_in[1];
    /* d_in[2] = y, unused */
    const float* lcas  = (const float*)d_in[3];
    const int*   trip1 = (const int*)d_in[4];
    const int*   trip2 = (const int*)d_in[5];
    const int*   trip3 = (const int*)d_in[6];
    const int*   trip4 = (const int*)d_in[7];
    const float* g1    = (const float*)d_in[8];
    const float* g2    = (const float*)d_in[9];
    const float* g3    = (const float*)d_in[10];
    const float* g4    = (const float*)d_in[11];

    k_poincare<<<32, 256>>>(lcas);
    k_dist_all<<<288, 256>>>(z_s, t_s);
    k_ghhc_all<<<NGBLK, 256>>>(trip1, trip2, trip3, trip4, g1, g2, g3, g4);
    k_final<<<1, 1>>>((float*)d_out);
}

// round 6
// speedup vs baseline: 1.5695x; 1.1015x over previous
#include <cuda_runtime.h>
#include <math.h>
#include <stdint.h>

#define BSZ   1024
#define NP    256
#define DIM   128
#define TB    51200      // triplets per batch segment (T1 == T3)
#define TL    12800      // triplets per lca segment   (T2 == T4)
#define TTOT  (2*TB + 2*TL)
#define NGBLK (TTOT / 8)

// ---------------- scratch (static device globals; no allocation) ------------
__device__ float  g_lh[NP * DIM];    // poincare-mapped lcas, row-major
__device__ float  g_lhT[DIM * NP];   // transposed for coalesced dist loads
__device__ float  g_y2[NP];          // ||lh||^2 per proxy
__device__ float  g_Dz[BSZ * NP];    // dist(z_s, lh)
__device__ float  g_Dt[BSZ * NP];    // dist(t_s, lh)
__device__ float  g_Dll[NP * NP];    // dist(lh, lh)

// ---------------- to_poincare: warp per row, shuffle reductions --------------
// Also zeroes the output scalar (blocks of ghhc accumulate into it directly).
__global__ __launch_bounds__(256) void k_poincare(const float* __restrict__ lcas,
                                                  float* __restrict__ outp) {
    const int warp = threadIdx.x >> 5;
    const int lane = threadIdx.x & 31;
    const int r    = blockIdx.x * 8 + warp;
    if (blockIdx.x == 0 && threadIdx.x == 0) outp[0] = 0.0f;

    float x[4];
    #pragma unroll
    for (int q = 0; q < 4; ++q) x[q] = lcas[r * DIM + lane + 32 * q];

    float s = 0.0f;
    #pragma unroll
    for (int q = 0; q < 4; ++q) s = fmaf(x[q], x[q], s);
    #pragma unroll
    for (int off = 16; off > 0; off >>= 1) s += __shfl_xor_sync(0xffffffffu, s, off);
    float xn = sqrtf(s) + 1e-5f;

    float scale = fminf(1.0f, 2.3f / xn);
    #pragma unroll
    for (int q = 0; q < 4; ++q) x[q] *= scale;

    s = 0.0f;
    #pragma unroll
    for (int q = 0; q < 4; ++q) s = fmaf(x[q], x[q], s);
    #pragma unroll
    for (int off = 16; off > 0; off >>= 1) s += __shfl_xor_sync(0xffffffffu, s, off);
    float xn2 = fmaxf(sqrtf(s), 1e-5f);

    const float sqrt_c = 0.31622776601683794f;   // sqrt(0.1)
    float arg = sqrt_c * xn2;
    float es  = tanhf(arg) / arg;                // expmap0 scale
    #pragma unroll
    for (int q = 0; q < 4; ++q) x[q] *= es;

    s = 0.0f;
    #pragma unroll
    for (int q = 0; q < 4; ++q) s = fmaf(x[q], x[q], s);
    #pragma unroll
    for (int off = 16; off > 0; off >>= 1) s += __shfl_xor_sync(0xffffffffu, s, off);
    float n3 = fmaxf(sqrtf(s), 1e-5f);
    const float maxn = (1.0f - 1e-3f) / 0.31622776601683794f;
    if (n3 > maxn) {
        float ps = maxn / n3;
        #pragma unroll
        for (int q = 0; q < 4; ++q) x[q] *= ps;
        s *= ps * ps;
    }

    #pragma unroll
    for (int q = 0; q < 4; ++q) {
        g_lh[r * DIM + lane + 32 * q]   = x[q];
        g_lhT[(lane + 32 * q) * NP + r] = x[q];
    }
    if (lane == 0) g_y2[r] = s;
}

// ---------------- fused distance matrices -----------------------------------
__global__ __launch_bounds__(256) void k_dist_all(const float* __restrict__ z,
                                                  const float* __restrict__ t) {
    __shared__ float xs[8 * DIM];
    __shared__ float sx2[8];
    const int b   = blockIdx.x;
    const int tid = threadIdx.x;

    const float* __restrict__ X;
    float* __restrict__ out;
    int r0;
    if (b < 128)      { X = z;    out = g_Dz;  r0 = b * 8; }
    else if (b < 256) { X = t;    out = g_Dt;  r0 = (b - 128) * 8; }
    else              { X = g_lh; out = g_Dll; r0 = (b - 256) * 8; }

    #pragma unroll
    for (int idx = tid; idx < 8 * DIM; idx += 256)
        xs[idx] = X[r0 * DIM + idx];
    __syncthreads();

    const int warp = tid >> 5, lane = tid & 31;
    {
        float s = 0.0f;
        #pragma unroll
        for (int q = 0; q < 4; ++q) {
            float e = xs[warp * DIM + lane + 32 * q];
            s = fmaf(e, e, s);
        }
        #pragma unroll
        for (int off = 16; off > 0; off >>= 1)
            s += __shfl_down_sync(0xffffffffu, s, off);
        if (lane == 0) sx2[warp] = s;
    }
    __syncthreads();

    const int col = tid;
    float acc[8] = {0,0,0,0,0,0,0,0};
    #pragma unroll 4
    for (int d = 0; d < DIM; ++d) {
        float yv = g_lhT[d * NP + col];
        #pragma unroll
        for (int r = 0; r < 8; ++r)
            acc[r] = fmaf(xs[r * DIM + d], yv, acc[r]);
    }

    const float y2 = g_y2[col];
    const float c  = 0.1f;
    #pragma unroll
    for (int r = 0; r < 8; ++r) {
        float x2    = sx2[r];
        float xy    = -acc[r];                               // (-x).y
        float a     = 1.0f + 2.0f * c * xy + c * y2;
        float bb    = 1.0f - c * x2;
        float denom = 1.0f + 2.0f * c * xy + (c * c) * x2 * y2;
        float numsq = a * a * x2 + 2.0f * a * bb * xy + bb * bb * y2;
        float nrm   = sqrtf(fmaxf(numsq, 1e-12f)) / fabsf(denom + 1e-5f);
        float v = 0.31622776601683794f * nrm;
        v = fminf(fmaxf(v, -0.99999f), 0.99999f);
        float art = 0.5f * (log1pf(v) - log1pf(-v));
        out[(r0 + r) * NP + col] = 6.324555320336759f * art;
    }
}

// ---------------- fused ghhc over all 4 triplet sets -------------------------
// One warp per triplet; lane owns 8 contiguous proxies. Phase-split (no spill).
// Gumbel loads use __ldcs (evict-first) so the zero-reuse 256MB stream doesn't
// evict the hot 2.3MB of D matrices. Block partial is atomically added
// (fire-and-forget, ONE atomic per block) straight into the output scalar.
__global__ __launch_bounds__(256, 4) void k_ghhc_all(
    const int*  __restrict__ t1, const int*  __restrict__ t2,
    const int*  __restrict__ t3, const int*  __restrict__ t4,
    const float* __restrict__ G1, const float* __restrict__ G2,
    const float* __restrict__ G3, const float* __restrict__ G4,
    float* __restrict__ outp) {
    __shared__ float wsum[8];
    const int warp = threadIdx.x >> 5;
    const int lane = threadIdx.x & 31;
    const int w    = blockIdx.x * 8 + warp;

    const int* trip; const float* g; const float* D; int T, t; float invT;
    if (w < TB)                { trip = t1; g = G1; D = g_Dz;  T = TB; t = w;                 invT = 1.0f / TB; }
    else if (w < TB + TL)      { trip = t2; g = G2; D = g_Dll; T = TL; t = w - TB;            invT = 1.0f / TL; }
    else if (w < 2*TB + TL)    { trip = t3; g = G3; D = g_Dt;  T = TB; t = w - (TB + TL);     invT = 1.0f / TB; }
    else                       { trip = t4; g = G4; D = g_Dll; T = TL; t = w - (2*TB + TL);   invT = 1.0f / TL; }

    const int i = trip[t];
    const int j = trip[T + t];
    const int k = trip[2 * T + t];
    const float* __restrict__ di = D + (size_t)i * NP;
    const float* __restrict__ dj = D + (size_t)j * NP;
    const float* __restrict__ dk = D + (size_t)k * NP;
    const float* __restrict__ g0 = g + (size_t)t * NP;
    const float* __restrict__ g1 = g + ((size_t)T + t) * NP;
    const int base = lane * 8;

    float m[8];
    float best0 = -INFINITY, best1 = -INFINITY;
    int   idx0 = 0, idx1 = 0;

    // ---- phase A: di, dj, g0 -> max_ij, score0 ----
    {
        float4 a0 = *(const float4*)(di + base), a1 = *(const float4*)(di + base + 4);
        float4 b0 = *(const float4*)(dj + base), b1 = *(const float4*)(dj + base + 4);
        float4 e0 = __ldcs((const float4*)(g0 + base));
        float4 e1 = __ldcs((const float4*)(g0 + base + 4));
        float av[8] = {a0.x, a0.y, a0.z, a0.w, a1.x, a1.y, a1.z, a1.w};
        float bv[8] = {b0.x, b0.y, b0.z, b0.w, b1.x, b1.y, b1.z, b1.w};
        float ev[8] = {e0.x, e0.y, e0.z, e0.w, e1.x, e1.y, e1.z, e1.w};
        #pragma unroll
        for (int u = 0; u < 8; ++u) {
            m[u] = fmaxf(av[u], bv[u]);
            float s0 = fmaf(m[u], -10.0f, ev[u]);     // g - max/tau
            if (s0 > best0) { best0 = s0; idx0 = base + u; }
        }
    }
    // ---- phase B: dk, g1 -> max_ijk, score1 ----
    {
        float4 c0 = *(const float4*)(dk + base), c1 = *(const float4*)(dk + base + 4);
        float4 f0 = __ldcs((const float4*)(g1 + base));
        float4 f1 = __ldcs((const float4*)(g1 + base + 4));
        float cv[8] = {c0.x, c0.y, c0.z, c0.w, c1.x, c1.y, c1.z, c1.w};
        float fv[8] = {f0.x, f0.y, f0.z, f0.w, f1.x, f1.y, f1.z, f1.w};
        #pragma unroll
        for (int u = 0; u < 8; ++u) {
            float m2 = fmaxf(cv[u], m[u]);
            float s1 = fmaf(m2, -10.0f, fv[u]);
            if (s1 > best1) { best1 = s1; idx1 = base + u; }
        }
    }

    // warp argmax reduce, first-occurrence (lowest index) wins ties
    #pragma unroll
    for (int off = 16; off > 0; off >>= 1) {
        float ov = __shfl_down_sync(0xffffffffu, best0, off);
        int   oi = __shfl_down_sync(0xffffffffu, idx0,  off);
        if (ov > best0 || (ov == best0 && oi < idx0)) { best0 = ov; idx0 = oi; }
        float ow = __shfl_down_sync(0xffffffffu, best1, off);
        int   oj = __shfl_down_sync(0xffffffffu, idx1,  off);
        if (ow > best1 || (ow == best1 && oj < idx1)) { best1 = ow; idx1 = oj; }
    }

    float hc = 0.0f;
    if (lane == 0 && idx0 != idx1) {                  // diff_lca gate
        float dia = di[idx0], dib = di[idx1];
        float dja = dj[idx0], djb = dj[idx1];
        float dka = dk[idx0], dkb = dk[idx1];
        float h = fmaxf(dia - dib + 0.1f, 0.0f)
                + fmaxf(dja - djb + 0.1f, 0.0f)
                + fmaxf(dkb - dka + 0.1f, 0.0f);
        hc = h * invT;
    }
    if (lane == 0) wsum[warp] = hc;
    __syncthreads();

    if (threadIdx.x == 0) {
        float s = 0.0f;
        #pragma unroll
        for (int q = 0; q < 8; ++q) s += wsum[q];
        atomicAdd(outp, s);                           // fire-and-forget
    }
}

// ---------------- launch -----------------------------------------------------
extern "C" void kernel_launch(void* const* d_in, const int* in_sizes, int n_in,
                              void* d_out, int out_size) {
    const float* z_s   = (const float*)d_in[0];
    const float* t_s   = (const float*)d_in[1];
    /* d_in[2] = y, unused */
    const float* lcas  = (const float*)d_in[3];
    const int*   trip1 = (const int*)d_in[4];
    const int*   trip2 = (const int*)d_in[5];
    const int*   trip3 = (const int*)d_in[6];
    const int*   trip4 = (const int*)d_in[7];
    const float* g1    = (const float*)d_in[8];
    const float* g2    = (const float*)d_in[9];
    const float* g3    = (const float*)d_in[10];
    const float* g4    = (const float*)d_in[11];

    k_poincare<<<32, 256>>>(lcas, (float*)d_out);
    k_dist_all<<<288, 256>>>(z_s, t_s);
    k_ghhc_all<<<NGBLK, 256>>>(trip1, trip2, trip3, trip4,
                               g1, g2, g3, g4, (float*)d_out);
}